// round 15
// baseline (speedup 1.0000x reference)
#include <cuda_runtime.h>
#include <cuda_bf16.h>
#include <cstdint>

// Problem constants
#define NCLS 64
#define NGRP 8
#define NSEQ 32
#define DIM  2048
#define OCH  256
#define NPRO 5
#define MTOT (NCLS * NGRP * NSEQ)   // 16384

// Scratch (device globals; no runtime allocation allowed)
__device__ __nv_bfloat16 g_ctxh[(size_t)MTOT * DIM];  // 67 MB (bf16 ctx)
__device__ float g_feats[(size_t)MTOT * DIM];         // 134 MB
__device__ float g_e[(size_t)MTOT * OCH];             // 16.8 MB
__device__ float g_pe[(size_t)NCLS * NPRO * OCH];
__device__ float g_q[(size_t)NCLS * NPRO * DIM];
__device__ float g_s[(size_t)NCLS * NPRO * OCH];
__device__ __nv_bfloat16 g_trh[(size_t)DIM * DIM];    // 8.4 MB (bf16 trans)
__device__ float g_w1r[(size_t)OCH * DIM];            // 2.1 MB (tf32 w1)

__device__ __forceinline__ float to_tf32(float x) {
    unsigned int t;
    asm("cvt.rna.tf32.f32 %0, %1;" : "=r"(t) : "f"(x));
    return __uint_as_float(t);
}

__device__ __forceinline__ unsigned int smem_u32(const void* p) {
    return (unsigned int)__cvta_generic_to_shared(p);
}

// ---------------------------------------------------------------------------
// kT: f32 -> tf32-rounded f32 (for w1). kTh: f32 -> bf16 (for trans).
// ---------------------------------------------------------------------------
__global__ __launch_bounds__(256) void kT(const float* __restrict__ src,
                                          float* __restrict__ dst, int n4)
{
    int i = blockIdx.x * blockDim.x + threadIdx.x;
    int stride = gridDim.x * blockDim.x;
    for (; i < n4; i += stride) {
        float4 v = ((const float4*)src)[i];
        v.x = to_tf32(v.x); v.y = to_tf32(v.y);
        v.z = to_tf32(v.z); v.w = to_tf32(v.w);
        ((float4*)dst)[i] = v;
    }
}

__global__ __launch_bounds__(256) void kTh(const float* __restrict__ src,
                                           __nv_bfloat16* __restrict__ dst, int n4)
{
    int i = blockIdx.x * blockDim.x + threadIdx.x;
    int stride = gridDim.x * blockDim.x;
    for (; i < n4; i += stride) {
        float4 v = ((const float4*)src)[i];
        __nv_bfloat162 lo = __floats2bfloat162_rn(v.x, v.y);
        __nv_bfloat162 hi = __floats2bfloat162_rn(v.z, v.w);
        ((__nv_bfloat162*)dst)[i * 2 + 0] = lo;
        ((__nv_bfloat162*)dst)[i * 2 + 1] = hi;
    }
}

#define KBS 20   // smem row stride in floats (kA1 only)

// ---------------------------------------------------------------------------
// Kernel A1: E = X @ w1r^T  (tf32 mma, unchanged, proven)
// ---------------------------------------------------------------------------
__global__ __launch_bounds__(256) void kA1(const float* __restrict__ Xin)
{
    __shared__ __align__(16) float As[2][128 * KBS];
    __shared__ __align__(16) float Bs[2][128 * KBS];

    const int tid  = threadIdx.x;
    const int lane = tid & 31;
    const int wid  = tid >> 5;
    const int wm   = (wid & 1) * 64;
    const int wn   = (wid >> 1) * 32;

    const int m0 = blockIdx.y * 128;
    const int n0 = blockIdx.x * 128;

    const float* Ab = Xin + (size_t)m0 * DIM;
    const float* Bb = g_w1r + (size_t)n0 * DIM;

    const int lrow0 = tid >> 2;
    const int lrow1 = (tid + 256) >> 2;
    const int lq    = (tid & 3) * 4;

    const unsigned int sA0 = smem_u32(&As[0][0]);
    const unsigned int sA1 = smem_u32(&As[1][0]);
    const unsigned int sB0 = smem_u32(&Bs[0][0]);
    const unsigned int sB1 = smem_u32(&Bs[1][0]);

#define CPA(dst_u32, srcp) \
    asm volatile("cp.async.cg.shared.global [%0], [%1], 16;" :: "r"(dst_u32), "l"(srcp) : "memory")

#define LOAD_TILE(bufA, bufB, k0_) do {                                              \
    CPA(bufA + (unsigned)(lrow0 * KBS + lq) * 4, Ab + (size_t)lrow0 * DIM + (k0_) + lq); \
    CPA(bufA + (unsigned)(lrow1 * KBS + lq) * 4, Ab + (size_t)lrow1 * DIM + (k0_) + lq); \
    CPA(bufB + (unsigned)(lrow0 * KBS + lq) * 4, Bb + (size_t)lrow0 * DIM + (k0_) + lq); \
    CPA(bufB + (unsigned)(lrow1 * KBS + lq) * 4, Bb + (size_t)lrow1 * DIM + (k0_) + lq); \
    asm volatile("cp.async.commit_group;" ::: "memory");                             \
} while (0)

    unsigned int offA[4];
#pragma unroll
    for (int mi = 0; mi < 4; ++mi)
        offA[mi] = (unsigned)((wm + mi * 16 + ((lane >> 3) & 1) * 8 + (lane & 7)) * KBS
                              + (lane >> 4) * 4);
    unsigned int offB[2];
#pragma unroll
    for (int pr = 0; pr < 2; ++pr)
        offB[pr] = (unsigned)((wn + pr * 16 + ((lane >> 4) & 1) * 8 + (lane & 7)) * KBS
                              + ((lane >> 3) & 1) * 4);

    float acc[4][4][4];
#pragma unroll
    for (int mi = 0; mi < 4; ++mi)
#pragma unroll
        for (int ni = 0; ni < 4; ++ni)
#pragma unroll
            for (int r = 0; r < 4; ++r) acc[mi][ni][r] = 0.f;

    LOAD_TILE(sA0, sB0, 0);

    const int NKT = DIM / 16;
    for (int kt = 0; kt < NKT; ++kt) {
        asm volatile("cp.async.wait_group 0;" ::: "memory");
        __syncthreads();

        const unsigned int aBase = (kt & 1) ? sA1 : sA0;
        const unsigned int bBase = (kt & 1) ? sB1 : sB0;

        if (kt + 1 < NKT) {
            const unsigned int aN = (kt & 1) ? sA0 : sA1;
            const unsigned int bN = (kt & 1) ? sB0 : sB1;
            LOAD_TILE(aN, bN, (kt + 1) * 16);
        }

#pragma unroll
        for (int kk = 0; kk < 16; kk += 8) {
            unsigned int af[4][4];
#pragma unroll
            for (int mi = 0; mi < 4; ++mi) {
                unsigned int addr = aBase + (offA[mi] + (unsigned)kk) * 4;
                asm volatile(
                    "ldmatrix.sync.aligned.m8n8.x4.shared.b16 {%0,%1,%2,%3}, [%4];"
                    : "=r"(af[mi][0]), "=r"(af[mi][1]), "=r"(af[mi][2]), "=r"(af[mi][3])
                    : "r"(addr));
#pragma unroll
                for (int j = 0; j < 4; ++j)
                    af[mi][j] = __float_as_uint(to_tf32(__uint_as_float(af[mi][j])));
            }
            unsigned int bf[4][2];
#pragma unroll
            for (int pr = 0; pr < 2; ++pr) {
                unsigned int addr = bBase + (offB[pr] + (unsigned)kk) * 4;
                asm volatile(
                    "ldmatrix.sync.aligned.m8n8.x4.shared.b16 {%0,%1,%2,%3}, [%4];"
                    : "=r"(bf[pr * 2][0]), "=r"(bf[pr * 2][1]),
                      "=r"(bf[pr * 2 + 1][0]), "=r"(bf[pr * 2 + 1][1])
                    : "r"(addr));
            }
#pragma unroll
            for (int mi = 0; mi < 4; ++mi)
#pragma unroll
                for (int ni = 0; ni < 4; ++ni) {
                    asm volatile(
                        "mma.sync.aligned.m16n8k8.row.col.f32.tf32.tf32.f32 "
                        "{%0,%1,%2,%3}, {%4,%5,%6,%7}, {%8,%9}, {%0,%1,%2,%3};"
                        : "+f"(acc[mi][ni][0]), "+f"(acc[mi][ni][1]),
                          "+f"(acc[mi][ni][2]), "+f"(acc[mi][ni][3])
                        : "r"(af[mi][0]), "r"(af[mi][1]), "r"(af[mi][2]), "r"(af[mi][3]),
                          "r"(bf[ni][0]), "r"(bf[ni][1]));
                }
        }
    }
#undef LOAD_TILE
#undef CPA

    float* Eb = g_e + (size_t)m0 * OCH + n0;
#pragma unroll
    for (int mi = 0; mi < 4; ++mi) {
        int r = wm + mi * 16 + (lane >> 2);
#pragma unroll
        for (int ni = 0; ni < 4; ++ni) {
            int cc = wn + ni * 8 + 2 * (lane & 3);
            *(float2*)(Eb + (size_t)r * OCH + cc) = make_float2(acc[mi][ni][0], acc[mi][ni][1]);
            *(float2*)(Eb + (size_t)(r + 8) * OCH + cc) = make_float2(acc[mi][ni][2], acc[mi][ni][3]);
        }
    }
}

// ---------------------------------------------------------------------------
// Kernel A2 (R7 fused): scores from E, softmax, ctx = att @ X -> bf16 ctx
// ---------------------------------------------------------------------------
__global__ __launch_bounds__(256) void kA2(const float* __restrict__ Xall)
{
    const int blk = blockIdx.x;
    const float* X  = Xall + (size_t)blk * NSEQ * DIM;
    const float* E  = g_e + (size_t)blk * NSEQ * OCH;
    __nv_bfloat16* CTX = g_ctxh + (size_t)blk * NSEQ * DIM;

    __shared__ __align__(16) float Ws[32][260];
    __shared__ __align__(16) float Ss[32][32];

    const int tid = threadIdx.x;

#pragma unroll
    for (int r = 0; r < 8; ++r) {
        int idx = r * 256 + tid;
        int row = idx >> 6;
        int c4  = idx & 63;
        float4 v = *(const float4*)(E + (size_t)row * OCH + c4 * 4);
        *(float4*)&Ws[row][c4 * 4] = v;
    }
    __syncthreads();

    {
        int n = tid >> 3;
        int mbase = (tid & 7) * 4;
        float s0 = 0.f, s1 = 0.f, s2 = 0.f, s3 = 0.f;
        for (int o = 0; o < OCH; o += 4) {
            float4 a  = *(const float4*)&Ws[n][o];
            float4 b0 = *(const float4*)&Ws[mbase + 0][o];
            float4 b1 = *(const float4*)&Ws[mbase + 1][o];
            float4 b2 = *(const float4*)&Ws[mbase + 2][o];
            float4 b3 = *(const float4*)&Ws[mbase + 3][o];
            s0 += a.x * b0.x + a.y * b0.y + a.z * b0.z + a.w * b0.w;
            s1 += a.x * b1.x + a.y * b1.y + a.z * b1.z + a.w * b1.w;
            s2 += a.x * b2.x + a.y * b2.y + a.z * b2.z + a.w * b2.w;
            s3 += a.x * b3.x + a.y * b3.y + a.z * b3.z + a.w * b3.w;
        }
        Ss[n][mbase + 0] = s0 * 0.0625f;
        Ss[n][mbase + 1] = s1 * 0.0625f;
        Ss[n][mbase + 2] = s2 * 0.0625f;
        Ss[n][mbase + 3] = s3 * 0.0625f;
    }
    __syncthreads();

    {
        int w = tid >> 5, lane = tid & 31;
#pragma unroll
        for (int rr = 0; rr < 4; ++rr) {
            int n = w * 4 + rr;
            float v = Ss[n][lane];
            float mx = v;
#pragma unroll
            for (int off = 16; off > 0; off >>= 1)
                mx = fmaxf(mx, __shfl_xor_sync(0xffffffffu, mx, off));
            float ex = expf(v - mx);
            float sm = ex;
#pragma unroll
            for (int off = 16; off > 0; off >>= 1)
                sm += __shfl_xor_sync(0xffffffffu, sm, off);
            Ss[n][lane] = ex / sm;
        }
    }
    __syncthreads();

    float* Xc = &Ws[0][0];
    const int XCS = 68;
    const int txc = tid & 63;
    const int tyc = tid >> 6;

    for (int d0 = 0; d0 < DIM; d0 += 64) {
#pragma unroll
        for (int r = 0; r < 2; ++r) {
            int idx = r * 256 + tid;
            int row = idx >> 4, c4 = idx & 15;
            float4 v = *(const float4*)(X + (size_t)row * DIM + d0 + c4 * 4);
            *(float4*)&Xc[row * XCS + c4 * 4] = v;
        }
        __syncthreads();

        float outv[8];
#pragma unroll
        for (int i = 0; i < 8; ++i) outv[i] = 0.f;

#pragma unroll
        for (int m4 = 0; m4 < 32; m4 += 4) {
            float xv0 = Xc[(m4 + 0) * XCS + txc];
            float xv1 = Xc[(m4 + 1) * XCS + txc];
            float xv2 = Xc[(m4 + 2) * XCS + txc];
            float xv3 = Xc[(m4 + 3) * XCS + txc];
#pragma unroll
            for (int i = 0; i < 8; ++i) {
                float4 a = *(const float4*)&Ss[tyc * 8 + i][m4];
                outv[i] += a.x * xv0 + a.y * xv1 + a.z * xv2 + a.w * xv3;
            }
        }
#pragma unroll
        for (int i = 0; i < 8; ++i)
            CTX[(size_t)(tyc * 8 + i) * DIM + d0 + txc] = __float2bfloat16_rn(outv[i]);
        __syncthreads();
    }
}

// ---------------------------------------------------------------------------
// Kernel B v7 (bf16, TM=256): Y = ctx @ trans^T, feats = X + relu(Y).
// 256x128 tile, 512 threads, 16 warps (warp tile 64x32 -- per-warp math
// byte-identical to v6), 2-stage, wait_group 0, 61 KB dynamic smem.
// Cuts B-side L2 traffic in half vs TM=128.
// ---------------------------------------------------------------------------
#define HBS 80             // smem row stride in BYTES (40 bf16)
#define HB_TM 256
#define HB_TN 128
#define HB_ASTG (HB_TM * HBS)   // 20480 B per A stage
#define HB_BSTG (HB_TN * HBS)   // 10240 B per B stage
#define HB_SMEM (2 * (HB_ASTG + HB_BSTG))  // 61440 B

__global__ __launch_bounds__(512) void kB(const float* __restrict__ X)
{
    extern __shared__ __align__(16) char hsm[];
    char* Abuf = hsm;                        // 2 stages of HB_ASTG
    char* Bbuf = hsm + 2 * HB_ASTG;          // 2 stages of HB_BSTG

    const int tid  = threadIdx.x;
    const int lane = tid & 31;
    const int wid  = tid >> 5;               // 0..15
    const int wm   = (wid & 3) * 64;         // 0,64,128,192
    const int wn   = (wid >> 2) * 32;        // 0,32,64,96

    const int m0 = blockIdx.y * HB_TM;
    const int n0 = blockIdx.x * HB_TN;

    const __nv_bfloat16* Ab = g_ctxh + (size_t)m0 * DIM;
    const __nv_bfloat16* Bb = g_trh + (size_t)n0 * DIM;

    // loader: A = 256 rows x 4 chunks = 1024 chunks -> 2/thread;
    //         B = 128 rows x 4 chunks =  512 chunks -> 1/thread.
    const int lrowA0 = tid >> 2;             // 0..127
    const int lrowA1 = 128 + (tid >> 2);     // 128..255
    const int lqb    = (tid & 3) * 16;       // byte offset in row
    const int lqe    = (tid & 3) * 8;        // element offset

    const unsigned int sA0 = smem_u32(Abuf);
    const unsigned int sA1 = smem_u32(Abuf + HB_ASTG);
    const unsigned int sB0 = smem_u32(Bbuf);
    const unsigned int sB1 = smem_u32(Bbuf + HB_BSTG);

#define CPA(dst_u32, srcp) \
    asm volatile("cp.async.cg.shared.global [%0], [%1], 16;" :: "r"(dst_u32), "l"(srcp) : "memory")

#define LOAD_TILE(bufA, bufB, k0_) do {                                              \
    CPA(bufA + (unsigned)(lrowA0 * HBS + lqb), Ab + (size_t)lrowA0 * DIM + (k0_) + lqe); \
    CPA(bufA + (unsigned)(lrowA1 * HBS + lqb), Ab + (size_t)lrowA1 * DIM + (k0_) + lqe); \
    CPA(bufB + (unsigned)(lrowA0 * HBS + lqb), Bb + (size_t)lrowA0 * DIM + (k0_) + lqe); \
    asm volatile("cp.async.commit_group;" ::: "memory");                             \
} while (0)

    unsigned int offA[4];
#pragma unroll
    for (int mi = 0; mi < 4; ++mi)
        offA[mi] = (unsigned)((wm + mi * 16 + ((lane >> 3) & 1) * 8 + (lane & 7)) * HBS
                              + ((lane >> 4) & 1) * 16);
    unsigned int offB[2];
#pragma unroll
    for (int pr = 0; pr < 2; ++pr)
        offB[pr] = (unsigned)((wn + pr * 16 + ((lane >> 4) & 1) * 8 + (lane & 7)) * HBS
                              + ((lane >> 3) & 1) * 16);

    float acc[4][4][4];
#pragma unroll
    for (int mi = 0; mi < 4; ++mi)
#pragma unroll
        for (int ni = 0; ni < 4; ++ni)
#pragma unroll
            for (int r = 0; r < 4; ++r) acc[mi][ni][r] = 0.f;

    LOAD_TILE(sA0, sB0, 0);

    const int NKT = DIM / 32;  // 64 tiles of 32 bf16
    for (int kt = 0; kt < NKT; ++kt) {
        asm volatile("cp.async.wait_group 0;" ::: "memory");
        __syncthreads();

        const unsigned int aBase = (kt & 1) ? sA1 : sA0;
        const unsigned int bBase = (kt & 1) ? sB1 : sB0;

        if (kt + 1 < NKT) {
            const unsigned int aN = (kt & 1) ? sA0 : sA1;
            const unsigned int bN = (kt & 1) ? sB0 : sB1;
            LOAD_TILE(aN, bN, (kt + 1) * 32);
        }

#pragma unroll
        for (int kk = 0; kk < 2; ++kk) {
            unsigned int af[4][4];
#pragma unroll
            for (int mi = 0; mi < 4; ++mi) {
                unsigned int addr = aBase + offA[mi] + (unsigned)kk * 32u;
                asm volatile(
                    "ldmatrix.sync.aligned.m8n8.x4.shared.b16 {%0,%1,%2,%3}, [%4];"
                    : "=r"(af[mi][0]), "=r"(af[mi][1]), "=r"(af[mi][2]), "=r"(af[mi][3])
                    : "r"(addr));
            }
            unsigned int bf[4][2];
#pragma unroll
            for (int pr = 0; pr < 2; ++pr) {
                unsigned int addr = bBase + offB[pr] + (unsigned)kk * 32u;
                asm volatile(
                    "ldmatrix.sync.aligned.m8n8.x4.shared.b16 {%0,%1,%2,%3}, [%4];"
                    : "=r"(bf[pr * 2][0]), "=r"(bf[pr * 2][1]),
                      "=r"(bf[pr * 2 + 1][0]), "=r"(bf[pr * 2 + 1][1])
                    : "r"(addr));
            }
#pragma unroll
            for (int mi = 0; mi < 4; ++mi)
#pragma unroll
                for (int ni = 0; ni < 4; ++ni) {
                    asm volatile(
                        "mma.sync.aligned.m16n8k16.row.col.f32.bf16.bf16.f32 "
                        "{%0,%1,%2,%3}, {%4,%5,%6,%7}, {%8,%9}, {%0,%1,%2,%3};"
                        : "+f"(acc[mi][ni][0]), "+f"(acc[mi][ni][1]),
                          "+f"(acc[mi][ni][2]), "+f"(acc[mi][ni][3])
                        : "r"(af[mi][0]), "r"(af[mi][1]), "r"(af[mi][2]), "r"(af[mi][3]),
                          "r"(bf[ni][0]), "r"(bf[ni][1]));
                }
        }
    }
#undef LOAD_TILE
#undef CPA

    // epilogue: feats = X + relu(Y)
    const float* Xb = X + (size_t)m0 * DIM + n0;
    float* Fb = g_feats + (size_t)m0 * DIM + n0;
#pragma unroll
    for (int mi = 0; mi < 4; ++mi) {
        int r  = wm + mi * 16 + (lane >> 2);
#pragma unroll
        for (int ni = 0; ni < 4; ++ni) {
            int cc = wn + ni * 8 + 2 * (lane & 3);
            {
                float2 xv = *(const float2*)(Xb + (size_t)r * DIM + cc);
                float2 o;
                o.x = xv.x + fmaxf(acc[mi][ni][0], 0.f);
                o.y = xv.y + fmaxf(acc[mi][ni][1], 0.f);
                *(float2*)(Fb + (size_t)r * DIM + cc) = o;
            }
            {
                int r2 = r + 8;
                float2 xv = *(const float2*)(Xb + (size_t)r2 * DIM + cc);
                float2 o;
                o.x = xv.x + fmaxf(acc[mi][ni][2], 0.f);
                o.y = xv.y + fmaxf(acc[mi][ni][3], 0.f);
                *(float2*)(Fb + (size_t)r2 * DIM + cc) = o;
            }
        }
    }
}

// ---------------------------------------------------------------------------
// kC1..kC4 (unchanged)
// ---------------------------------------------------------------------------
__global__ __launch_bounds__(256) void kC1(const float* __restrict__ protos,
                                           const float* __restrict__ w2i)
{
    const int c  = blockIdx.y;
    const int o0 = blockIdx.x * 32;
    __shared__ __align__(16) float prs[NPRO * DIM];

    const int tid = threadIdx.x;
    const int lane = tid & 31;
    const int w = tid >> 5;

    {
        const float4* src = (const float4*)(protos + (size_t)c * NPRO * DIM);
        float4* dst = (float4*)prs;
        for (int i = tid; i < NPRO * DIM / 4; i += 256) dst[i] = src[i];
    }
    __syncthreads();

#pragma unroll
    for (int oi = 0; oi < 4; ++oi) {
        int o = o0 + w * 4 + oi;
        float acc[NPRO] = {0.f, 0.f, 0.f, 0.f, 0.f};
        for (int d = lane; d < DIM; d += 32) {
            float wv = w2i[(size_t)o * DIM + d];
#pragma unroll
            for (int p = 0; p < NPRO; ++p) acc[p] += prs[p * DIM + d] * wv;
        }
#pragma unroll
        for (int p = 0; p < NPRO; ++p) {
#pragma unroll
            for (int off = 16; off > 0; off >>= 1)
                acc[p] += __shfl_xor_sync(0xffffffffu, acc[p], off);
        }
        if (lane == 0) {
#pragma unroll
            for (int p = 0; p < NPRO; ++p)
                g_pe[((size_t)c * NPRO + p) * OCH + o] = acc[p];
        }
    }
}

__global__ __launch_bounds__(256) void kC2(const float* __restrict__ w1i)
{
    const int c  = blockIdx.y;
    const int d0 = blockIdx.x * 256;
    __shared__ __align__(16) float pes[NPRO * OCH];

    const int tid = threadIdx.x;
    {
        const float4* src = (const float4*)(g_pe + (size_t)c * NPRO * OCH);
        float4* dst = (float4*)pes;
        for (int i = tid; i < NPRO * OCH / 4; i += 256) dst[i] = src[i];
    }
    __syncthreads();

    const int d = d0 + tid;
    float acc[NPRO] = {0.f, 0.f, 0.f, 0.f, 0.f};
#pragma unroll 8
    for (int o = 0; o < OCH; ++o) {
        float wv = w1i[(size_t)o * DIM + d];
#pragma unroll
        for (int p = 0; p < NPRO; ++p) acc[p] += pes[p * OCH + o] * wv;
    }
#pragma unroll
    for (int p = 0; p < NPRO; ++p)
        g_q[((size_t)c * NPRO + p) * DIM + d] = acc[p];
}

__global__ __launch_bounds__(256) void kC3()
{
    const int c  = blockIdx.y;
    const int n0 = blockIdx.x * 32;
    __shared__ __align__(16) float qsm[NPRO * DIM];

    const int tid = threadIdx.x;
    const int lane = tid & 31;
    const int w = tid >> 5;
    const float* F = g_feats + (size_t)c * (NGRP * NSEQ) * DIM;

    {
        const float4* src = (const float4*)(g_q + (size_t)c * NPRO * DIM);
        float4* dst = (float4*)qsm;
        for (int i = tid; i < NPRO * DIM / 4; i += 256) dst[i] = src[i];
    }
    __syncthreads();

#pragma unroll
    for (int ni = 0; ni < 4; ++ni) {
        int n = n0 + w * 4 + ni;
        const float* fr = F + (size_t)n * DIM;
        float acc[NPRO] = {0.f, 0.f, 0.f, 0.f, 0.f};
        for (int d = lane; d < DIM; d += 32) {
            float fv = fr[d];
#pragma unroll
            for (int p = 0; p < NPRO; ++p) acc[p] += fv * qsm[p * DIM + d];
        }
#pragma unroll
        for (int p = 0; p < NPRO; ++p) {
#pragma unroll
            for (int off = 16; off > 0; off >>= 1)
                acc[p] += __shfl_xor_sync(0xffffffffu, acc[p], off);
        }
        if (lane == 0) {
#pragma unroll
            for (int p = 0; p < NPRO; ++p)
                g_s[((size_t)c * NPRO + p) * OCH + n] = acc[p] * 0.0625f;
        }
    }
}

__global__ __launch_bounds__(256) void kC4(float* __restrict__ outp)
{
    const int c  = blockIdx.y;
    const int d0 = blockIdx.x * 256;
    __shared__ __align__(16) float att[NPRO * OCH];

    const int tid = threadIdx.x;
    const int lane = tid & 31;
    const int w = tid >> 5;
    const float* F = g_feats + (size_t)c * (NGRP * NSEQ) * DIM;

    {
        const float4* src = (const float4*)(g_s + (size_t)c * NPRO * OCH);
        float4* dst = (float4*)att;
        for (int i = tid; i < NPRO * OCH / 4; i += 256) dst[i] = src[i];
    }
    __syncthreads();

    if (w < NPRO) {
        const int p = w;
        float mx = -1e30f;
        for (int n = lane; n < OCH; n += 32) mx = fmaxf(mx, att[p * OCH + n]);
#pragma unroll
        for (int off = 16; off > 0; off >>= 1)
            mx = fmaxf(mx, __shfl_xor_sync(0xffffffffu, mx, off));
        float sm = 0.f;
        for (int n = lane; n < OCH; n += 32) {
            float e = expf(att[p * OCH + n] - mx);
            att[p * OCH + n] = e;
            sm += e;
        }
#pragma unroll
        for (int off = 16; off > 0; off >>= 1)
            sm += __shfl_xor_sync(0xffffffffu, sm, off);
        float inv = 1.f / sm;
        for (int n = lane; n < OCH; n += 32) att[p * OCH + n] *= inv;
    }
    __syncthreads();

    const int d = d0 + tid;
    float acc[NPRO] = {0.f, 0.f, 0.f, 0.f, 0.f};
#pragma unroll 8
    for (int n = 0; n < OCH; ++n) {
        float fv = F[(size_t)n * DIM + d];
#pragma unroll
        for (int p = 0; p < NPRO; ++p) acc[p] += att[p * OCH + n] * fv;
    }
    float* ob = outp + (size_t)c * NPRO * DIM;
#pragma unroll
    for (int p = 0; p < NPRO; ++p) ob[(size_t)p * DIM + d] = acc[p];
}

// ---------------------------------------------------------------------------
extern "C" void kernel_launch(void* const* d_in, const int* in_sizes, int n_in,
                              void* d_out, int out_size)
{
    const float* topk   = (const float*)d_in[0];  // [64,8,32,2048]
    const float* protos = (const float*)d_in[1];  // [64,5,2048]
    const float* w1     = (const float*)d_in[2];  // [256,2048]
    const float* trans  = (const float*)d_in[3];  // [2048,2048]
    const float* w1i    = (const float*)d_in[4];  // [256,2048]
    const float* w2i    = (const float*)d_in[5];  // [256,2048]
    float* out = (float*)d_out;

    // pre-convert weights: trans -> bf16, w1 -> tf32
    __nv_bfloat16* trh = nullptr; cudaGetSymbolAddress((void**)&trh, g_trh);
    float* w1r = nullptr; cudaGetSymbolAddress((void**)&w1r, g_w1r);
    kTh<<<1024, 256>>>(trans, trh, DIM * DIM / 4);
    kT<<<64, 256>>>(w1, w1r, OCH * DIM / 4);

    dim3 gA1(OCH / 128, MTOT / 128);  // (2, 128)
    kA1<<<gA1, 256>>>(topk);
    kA2<<<NCLS * NGRP, 256>>>(topk);

    cudaFuncSetAttribute(kB, cudaFuncAttributeMaxDynamicSharedMemorySize, HB_SMEM);
    dim3 gB(DIM / HB_TN, MTOT / HB_TM);   // (16, 64)
    kB<<<gB, 512, HB_SMEM>>>(topk);

    dim3 gC(8, NCLS);                 // (8, 64)
    kC1<<<gC, 256>>>(protos, w2i);
    kC2<<<gC, 256>>>(w1i);
    kC3<<<gC, 256>>>();
    kC4<<<gC, 256>>>(out);
}

// round 16
// speedup vs baseline: 1.0907x; 1.0907x over previous
#include <cuda_runtime.h>
#include <cuda_bf16.h>
#include <cstdint>

// Problem constants
#define NCLS 64
#define NGRP 8
#define NSEQ 32
#define DIM  2048
#define OCH  256
#define NPRO 5
#define MTOT (NCLS * NGRP * NSEQ)   // 16384

// Scratch (device globals; no runtime allocation allowed)
__device__ __nv_bfloat16 g_ctxh[(size_t)MTOT * DIM];  // 67 MB (bf16 ctx)
__device__ float g_feats[(size_t)MTOT * DIM];         // 134 MB
__device__ float g_e[(size_t)MTOT * OCH];             // 16.8 MB
__device__ float g_pe[(size_t)NCLS * NPRO * OCH];
__device__ float g_q[(size_t)NCLS * NPRO * DIM];
__device__ float g_s[(size_t)NCLS * NPRO * OCH];
__device__ __nv_bfloat16 g_trh[(size_t)DIM * DIM];    // 8.4 MB (bf16 trans)
__device__ float g_w1r[(size_t)OCH * DIM];            // 2.1 MB (tf32 w1)

__device__ __forceinline__ float to_tf32(float x) {
    unsigned int t;
    asm("cvt.rna.tf32.f32 %0, %1;" : "=r"(t) : "f"(x));
    return __uint_as_float(t);
}

__device__ __forceinline__ unsigned int smem_u32(const void* p) {
    return (unsigned int)__cvta_generic_to_shared(p);
}

// ---------------------------------------------------------------------------
// kT: f32 -> tf32-rounded f32 (for w1). kTh: f32 -> bf16 (for trans).
// ---------------------------------------------------------------------------
__global__ __launch_bounds__(256) void kT(const float* __restrict__ src,
                                          float* __restrict__ dst, int n4)
{
    int i = blockIdx.x * blockDim.x + threadIdx.x;
    int stride = gridDim.x * blockDim.x;
    for (; i < n4; i += stride) {
        float4 v = ((const float4*)src)[i];
        v.x = to_tf32(v.x); v.y = to_tf32(v.y);
        v.z = to_tf32(v.z); v.w = to_tf32(v.w);
        ((float4*)dst)[i] = v;
    }
}

__global__ __launch_bounds__(256) void kTh(const float* __restrict__ src,
                                           __nv_bfloat16* __restrict__ dst, int n4)
{
    int i = blockIdx.x * blockDim.x + threadIdx.x;
    int stride = gridDim.x * blockDim.x;
    for (; i < n4; i += stride) {
        float4 v = ((const float4*)src)[i];
        __nv_bfloat162 lo = __floats2bfloat162_rn(v.x, v.y);
        __nv_bfloat162 hi = __floats2bfloat162_rn(v.z, v.w);
        ((__nv_bfloat162*)dst)[i * 2 + 0] = lo;
        ((__nv_bfloat162*)dst)[i * 2 + 1] = hi;
    }
}

#define KBS 20   // smem row stride in floats (kA1 only)

// ---------------------------------------------------------------------------
// Kernel A1: E = X @ w1r^T  (tf32 mma, unchanged, proven)
// ---------------------------------------------------------------------------
__global__ __launch_bounds__(256) void kA1(const float* __restrict__ Xin)
{
    __shared__ __align__(16) float As[2][128 * KBS];
    __shared__ __align__(16) float Bs[2][128 * KBS];

    const int tid  = threadIdx.x;
    const int lane = tid & 31;
    const int wid  = tid >> 5;
    const int wm   = (wid & 1) * 64;
    const int wn   = (wid >> 1) * 32;

    const int m0 = blockIdx.y * 128;
    const int n0 = blockIdx.x * 128;

    const float* Ab = Xin + (size_t)m0 * DIM;
    const float* Bb = g_w1r + (size_t)n0 * DIM;

    const int lrow0 = tid >> 2;
    const int lrow1 = (tid + 256) >> 2;
    const int lq    = (tid & 3) * 4;

    const unsigned int sA0 = smem_u32(&As[0][0]);
    const unsigned int sA1 = smem_u32(&As[1][0]);
    const unsigned int sB0 = smem_u32(&Bs[0][0]);
    const unsigned int sB1 = smem_u32(&Bs[1][0]);

#define CPA(dst_u32, srcp) \
    asm volatile("cp.async.cg.shared.global [%0], [%1], 16;" :: "r"(dst_u32), "l"(srcp) : "memory")

#define LOAD_TILE(bufA, bufB, k0_) do {                                              \
    CPA(bufA + (unsigned)(lrow0 * KBS + lq) * 4, Ab + (size_t)lrow0 * DIM + (k0_) + lq); \
    CPA(bufA + (unsigned)(lrow1 * KBS + lq) * 4, Ab + (size_t)lrow1 * DIM + (k0_) + lq); \
    CPA(bufB + (unsigned)(lrow0 * KBS + lq) * 4, Bb + (size_t)lrow0 * DIM + (k0_) + lq); \
    CPA(bufB + (unsigned)(lrow1 * KBS + lq) * 4, Bb + (size_t)lrow1 * DIM + (k0_) + lq); \
    asm volatile("cp.async.commit_group;" ::: "memory");                             \
} while (0)

    unsigned int offA[4];
#pragma unroll
    for (int mi = 0; mi < 4; ++mi)
        offA[mi] = (unsigned)((wm + mi * 16 + ((lane >> 3) & 1) * 8 + (lane & 7)) * KBS
                              + (lane >> 4) * 4);
    unsigned int offB[2];
#pragma unroll
    for (int pr = 0; pr < 2; ++pr)
        offB[pr] = (unsigned)((wn + pr * 16 + ((lane >> 4) & 1) * 8 + (lane & 7)) * KBS
                              + ((lane >> 3) & 1) * 4);

    float acc[4][4][4];
#pragma unroll
    for (int mi = 0; mi < 4; ++mi)
#pragma unroll
        for (int ni = 0; ni < 4; ++ni)
#pragma unroll
            for (int r = 0; r < 4; ++r) acc[mi][ni][r] = 0.f;

    LOAD_TILE(sA0, sB0, 0);

    const int NKT = DIM / 16;
    for (int kt = 0; kt < NKT; ++kt) {
        asm volatile("cp.async.wait_group 0;" ::: "memory");
        __syncthreads();

        const unsigned int aBase = (kt & 1) ? sA1 : sA0;
        const unsigned int bBase = (kt & 1) ? sB1 : sB0;

        if (kt + 1 < NKT) {
            const unsigned int aN = (kt & 1) ? sA0 : sA1;
            const unsigned int bN = (kt & 1) ? sB0 : sB1;
            LOAD_TILE(aN, bN, (kt + 1) * 16);
        }

#pragma unroll
        for (int kk = 0; kk < 16; kk += 8) {
            unsigned int af[4][4];
#pragma unroll
            for (int mi = 0; mi < 4; ++mi) {
                unsigned int addr = aBase + (offA[mi] + (unsigned)kk) * 4;
                asm volatile(
                    "ldmatrix.sync.aligned.m8n8.x4.shared.b16 {%0,%1,%2,%3}, [%4];"
                    : "=r"(af[mi][0]), "=r"(af[mi][1]), "=r"(af[mi][2]), "=r"(af[mi][3])
                    : "r"(addr));
#pragma unroll
                for (int j = 0; j < 4; ++j)
                    af[mi][j] = __float_as_uint(to_tf32(__uint_as_float(af[mi][j])));
            }
            unsigned int bf[4][2];
#pragma unroll
            for (int pr = 0; pr < 2; ++pr) {
                unsigned int addr = bBase + (offB[pr] + (unsigned)kk) * 4;
                asm volatile(
                    "ldmatrix.sync.aligned.m8n8.x4.shared.b16 {%0,%1,%2,%3}, [%4];"
                    : "=r"(bf[pr * 2][0]), "=r"(bf[pr * 2][1]),
                      "=r"(bf[pr * 2 + 1][0]), "=r"(bf[pr * 2 + 1][1])
                    : "r"(addr));
            }
#pragma unroll
            for (int mi = 0; mi < 4; ++mi)
#pragma unroll
                for (int ni = 0; ni < 4; ++ni) {
                    asm volatile(
                        "mma.sync.aligned.m16n8k8.row.col.f32.tf32.tf32.f32 "
                        "{%0,%1,%2,%3}, {%4,%5,%6,%7}, {%8,%9}, {%0,%1,%2,%3};"
                        : "+f"(acc[mi][ni][0]), "+f"(acc[mi][ni][1]),
                          "+f"(acc[mi][ni][2]), "+f"(acc[mi][ni][3])
                        : "r"(af[mi][0]), "r"(af[mi][1]), "r"(af[mi][2]), "r"(af[mi][3]),
                          "r"(bf[ni][0]), "r"(bf[ni][1]));
                }
        }
    }
#undef LOAD_TILE
#undef CPA

    float* Eb = g_e + (size_t)m0 * OCH + n0;
#pragma unroll
    for (int mi = 0; mi < 4; ++mi) {
        int r = wm + mi * 16 + (lane >> 2);
#pragma unroll
        for (int ni = 0; ni < 4; ++ni) {
            int cc = wn + ni * 8 + 2 * (lane & 3);
            *(float2*)(Eb + (size_t)r * OCH + cc) = make_float2(acc[mi][ni][0], acc[mi][ni][1]);
            *(float2*)(Eb + (size_t)(r + 8) * OCH + cc) = make_float2(acc[mi][ni][2], acc[mi][ni][3]);
        }
    }
}

// ---------------------------------------------------------------------------
// Kernel A2: scores from E (conflict-free mapping), softmax, ctx -> bf16.
// Score-phase b-loads now read 8 CONSECUTIVE rows per instruction
// (bank offsets 0,4,...,28 at stride 260 -> no conflicts). Per-element
// dot-product order unchanged -> bit-identical results.
// ---------------------------------------------------------------------------
__global__ __launch_bounds__(256) void kA2(const float* __restrict__ Xall)
{
    const int blk = blockIdx.x;
    const float* X  = Xall + (size_t)blk * NSEQ * DIM;
    const float* E  = g_e + (size_t)blk * NSEQ * OCH;
    __nv_bfloat16* CTX = g_ctxh + (size_t)blk * NSEQ * DIM;

    __shared__ __align__(16) float Ws[32][260];
    __shared__ __align__(16) float Ss[32][32];

    const int tid = threadIdx.x;

#pragma unroll
    for (int r = 0; r < 8; ++r) {
        int idx = r * 256 + tid;
        int row = idx >> 6;
        int c4  = idx & 63;
        float4 v = *(const float4*)(E + (size_t)row * OCH + c4 * 4);
        *(float4*)&Ws[row][c4 * 4] = v;
    }
    __syncthreads();

    {
        int n  = tid >> 3;
        int mb = tid & 7;     // consecutive rows across the 8-lane group
        float s0 = 0.f, s1 = 0.f, s2 = 0.f, s3 = 0.f;
        for (int o = 0; o < OCH; o += 4) {
            float4 a  = *(const float4*)&Ws[n][o];
            float4 b0 = *(const float4*)&Ws[mb +  0][o];
            float4 b1 = *(const float4*)&Ws[mb +  8][o];
            float4 b2 = *(const float4*)&Ws[mb + 16][o];
            float4 b3 = *(const float4*)&Ws[mb + 24][o];
            s0 += a.x * b0.x + a.y * b0.y + a.z * b0.z + a.w * b0.w;
            s1 += a.x * b1.x + a.y * b1.y + a.z * b1.z + a.w * b1.w;
            s2 += a.x * b2.x + a.y * b2.y + a.z * b2.z + a.w * b2.w;
            s3 += a.x * b3.x + a.y * b3.y + a.z * b3.z + a.w * b3.w;
        }
        Ss[n][mb +  0] = s0 * 0.0625f;
        Ss[n][mb +  8] = s1 * 0.0625f;
        Ss[n][mb + 16] = s2 * 0.0625f;
        Ss[n][mb + 24] = s3 * 0.0625f;
    }
    __syncthreads();

    {
        int w = tid >> 5, lane = tid & 31;
#pragma unroll
        for (int rr = 0; rr < 4; ++rr) {
            int n = w * 4 + rr;
            float v = Ss[n][lane];
            float mx = v;
#pragma unroll
            for (int off = 16; off > 0; off >>= 1)
                mx = fmaxf(mx, __shfl_xor_sync(0xffffffffu, mx, off));
            float ex = expf(v - mx);
            float sm = ex;
#pragma unroll
            for (int off = 16; off > 0; off >>= 1)
                sm += __shfl_xor_sync(0xffffffffu, sm, off);
            Ss[n][lane] = ex / sm;
        }
    }
    __syncthreads();

    float* Xc = &Ws[0][0];
    const int XCS = 68;
    const int txc = tid & 63;
    const int tyc = tid >> 6;

    for (int d0 = 0; d0 < DIM; d0 += 64) {
#pragma unroll
        for (int r = 0; r < 2; ++r) {
            int idx = r * 256 + tid;
            int row = idx >> 4, c4 = idx & 15;
            float4 v = *(const float4*)(X + (size_t)row * DIM + d0 + c4 * 4);
            *(float4*)&Xc[row * XCS + c4 * 4] = v;
        }
        __syncthreads();

        float outv[8];
#pragma unroll
        for (int i = 0; i < 8; ++i) outv[i] = 0.f;

#pragma unroll
        for (int m4 = 0; m4 < 32; m4 += 4) {
            float xv0 = Xc[(m4 + 0) * XCS + txc];
            float xv1 = Xc[(m4 + 1) * XCS + txc];
            float xv2 = Xc[(m4 + 2) * XCS + txc];
            float xv3 = Xc[(m4 + 3) * XCS + txc];
#pragma unroll
            for (int i = 0; i < 8; ++i) {
                float4 a = *(const float4*)&Ss[tyc * 8 + i][m4];
                outv[i] += a.x * xv0 + a.y * xv1 + a.z * xv2 + a.w * xv3;
            }
        }
#pragma unroll
        for (int i = 0; i < 8; ++i)
            CTX[(size_t)(tyc * 8 + i) * DIM + d0 + txc] = __float2bfloat16_rn(outv[i]);
        __syncthreads();
    }
}

// ---------------------------------------------------------------------------
// Kernel B (R14 winner, bf16 m16n8k16, 128x128, 256 thr): restored exactly.
// ---------------------------------------------------------------------------
#define HBS 80   // smem row stride in BYTES (40 bf16)
#define HSTG (128 * HBS)  // 10240 bytes per operand stage

__global__ __launch_bounds__(256) void kB(const float* __restrict__ X)
{
    __shared__ __align__(16) char As[2][HSTG];
    __shared__ __align__(16) char Bs[2][HSTG];

    const int tid  = threadIdx.x;
    const int lane = tid & 31;
    const int wid  = tid >> 5;
    const int wm   = (wid & 1) * 64;
    const int wn   = (wid >> 1) * 32;

    const int m0 = blockIdx.y * 128;
    const int n0 = blockIdx.x * 128;

    const __nv_bfloat16* Ab = g_ctxh + (size_t)m0 * DIM;
    const __nv_bfloat16* Bb = g_trh + (size_t)n0 * DIM;

    const int lrow0 = tid >> 2;
    const int lrow1 = 64 + (tid >> 2);
    const int lqb   = (tid & 3) * 16;
    const int lqe   = (tid & 3) * 8;

    const unsigned int sA0 = smem_u32(&As[0][0]);
    const unsigned int sA1 = smem_u32(&As[1][0]);
    const unsigned int sB0 = smem_u32(&Bs[0][0]);
    const unsigned int sB1 = smem_u32(&Bs[1][0]);

#define CPA(dst_u32, srcp) \
    asm volatile("cp.async.cg.shared.global [%0], [%1], 16;" :: "r"(dst_u32), "l"(srcp) : "memory")

#define LOAD_TILE(bufA, bufB, k0_) do {                                            \
    CPA(bufA + (unsigned)(lrow0 * HBS + lqb), Ab + (size_t)lrow0 * DIM + (k0_) + lqe); \
    CPA(bufA + (unsigned)(lrow1 * HBS + lqb), Ab + (size_t)lrow1 * DIM + (k0_) + lqe); \
    CPA(bufB + (unsigned)(lrow0 * HBS + lqb), Bb + (size_t)lrow0 * DIM + (k0_) + lqe); \
    CPA(bufB + (unsigned)(lrow1 * HBS + lqb), Bb + (size_t)lrow1 * DIM + (k0_) + lqe); \
    asm volatile("cp.async.commit_group;" ::: "memory");                           \
} while (0)

    unsigned int offA[4];
#pragma unroll
    for (int mi = 0; mi < 4; ++mi)
        offA[mi] = (unsigned)((wm + mi * 16 + ((lane >> 3) & 1) * 8 + (lane & 7)) * HBS
                              + ((lane >> 4) & 1) * 16);
    unsigned int offB[2];
#pragma unroll
    for (int pr = 0; pr < 2; ++pr)
        offB[pr] = (unsigned)((wn + pr * 16 + ((lane >> 4) & 1) * 8 + (lane & 7)) * HBS
                              + ((lane >> 3) & 1) * 16);

    float acc[4][4][4];
#pragma unroll
    for (int mi = 0; mi < 4; ++mi)
#pragma unroll
        for (int ni = 0; ni < 4; ++ni)
#pragma unroll
            for (int r = 0; r < 4; ++r) acc[mi][ni][r] = 0.f;

    LOAD_TILE(sA0, sB0, 0);

    const int NKT = DIM / 32;  // 64 tiles of 32 bf16
    for (int kt = 0; kt < NKT; ++kt) {
        asm volatile("cp.async.wait_group 0;" ::: "memory");
        __syncthreads();

        const unsigned int aBase = (kt & 1) ? sA1 : sA0;
        const unsigned int bBase = (kt & 1) ? sB1 : sB0;

        if (kt + 1 < NKT) {
            const unsigned int aN = (kt & 1) ? sA0 : sA1;
            const unsigned int bN = (kt & 1) ? sB0 : sB1;
            LOAD_TILE(aN, bN, (kt + 1) * 32);
        }

#pragma unroll
        for (int kk = 0; kk < 2; ++kk) {
            unsigned int af[4][4];
#pragma unroll
            for (int mi = 0; mi < 4; ++mi) {
                unsigned int addr = aBase + offA[mi] + (unsigned)kk * 32u;
                asm volatile(
                    "ldmatrix.sync.aligned.m8n8.x4.shared.b16 {%0,%1,%2,%3}, [%4];"
                    : "=r"(af[mi][0]), "=r"(af[mi][1]), "=r"(af[mi][2]), "=r"(af[mi][3])
                    : "r"(addr));
            }
            unsigned int bf[4][2];
#pragma unroll
            for (int pr = 0; pr < 2; ++pr) {
                unsigned int addr = bBase + offB[pr] + (unsigned)kk * 32u;
                asm volatile(
                    "ldmatrix.sync.aligned.m8n8.x4.shared.b16 {%0,%1,%2,%3}, [%4];"
                    : "=r"(bf[pr * 2][0]), "=r"(bf[pr * 2][1]),
                      "=r"(bf[pr * 2 + 1][0]), "=r"(bf[pr * 2 + 1][1])
                    : "r"(addr));
            }
#pragma unroll
            for (int mi = 0; mi < 4; ++mi)
#pragma unroll
                for (int ni = 0; ni < 4; ++ni) {
                    asm volatile(
                        "mma.sync.aligned.m16n8k16.row.col.f32.bf16.bf16.f32 "
                        "{%0,%1,%2,%3}, {%4,%5,%6,%7}, {%8,%9}, {%0,%1,%2,%3};"
                        : "+f"(acc[mi][ni][0]), "+f"(acc[mi][ni][1]),
                          "+f"(acc[mi][ni][2]), "+f"(acc[mi][ni][3])
                        : "r"(af[mi][0]), "r"(af[mi][1]), "r"(af[mi][2]), "r"(af[mi][3]),
                          "r"(bf[ni][0]), "r"(bf[ni][1]));
                }
        }
    }
#undef LOAD_TILE
#undef CPA

    const float* Xb = X + (size_t)m0 * DIM + n0;
    float* Fb = g_feats + (size_t)m0 * DIM + n0;
#pragma unroll
    for (int mi = 0; mi < 4; ++mi) {
        int r  = wm + mi * 16 + (lane >> 2);
#pragma unroll
        for (int ni = 0; ni < 4; ++ni) {
            int cc = wn + ni * 8 + 2 * (lane & 3);
            {
                float2 xv = *(const float2*)(Xb + (size_t)r * DIM + cc);
                float2 o;
                o.x = xv.x + fmaxf(acc[mi][ni][0], 0.f);
                o.y = xv.y + fmaxf(acc[mi][ni][1], 0.f);
                *(float2*)(Fb + (size_t)r * DIM + cc) = o;
            }
            {
                int r2 = r + 8;
                float2 xv = *(const float2*)(Xb + (size_t)r2 * DIM + cc);
                float2 o;
                o.x = xv.x + fmaxf(acc[mi][ni][2], 0.f);
                o.y = xv.y + fmaxf(acc[mi][ni][3], 0.f);
                *(float2*)(Fb + (size_t)r2 * DIM + cc) = o;
            }
        }
    }
}

// ---------------------------------------------------------------------------
// kC1..kC4 (unchanged)
// ---------------------------------------------------------------------------
__global__ __launch_bounds__(256) void kC1(const float* __restrict__ protos,
                                           const float* __restrict__ w2i)
{
    const int c  = blockIdx.y;
    const int o0 = blockIdx.x * 32;
    __shared__ __align__(16) float prs[NPRO * DIM];

    const int tid = threadIdx.x;
    const int lane = tid & 31;
    const int w = tid >> 5;

    {
        const float4* src = (const float4*)(protos + (size_t)c * NPRO * DIM);
        float4* dst = (float4*)prs;
        for (int i = tid; i < NPRO * DIM / 4; i += 256) dst[i] = src[i];
    }
    __syncthreads();

#pragma unroll
    for (int oi = 0; oi < 4; ++oi) {
        int o = o0 + w * 4 + oi;
        float acc[NPRO] = {0.f, 0.f, 0.f, 0.f, 0.f};
        for (int d = lane; d < DIM; d += 32) {
            float wv = w2i[(size_t)o * DIM + d];
#pragma unroll
            for (int p = 0; p < NPRO; ++p) acc[p] += prs[p * DIM + d] * wv;
        }
#pragma unroll
        for (int p = 0; p < NPRO; ++p) {
#pragma unroll
            for (int off = 16; off > 0; off >>= 1)
                acc[p] += __shfl_xor_sync(0xffffffffu, acc[p], off);
        }
        if (lane == 0) {
#pragma unroll
            for (int p = 0; p < NPRO; ++p)
                g_pe[((size_t)c * NPRO + p) * OCH + o] = acc[p];
        }
    }
}

__global__ __launch_bounds__(256) void kC2(const float* __restrict__ w1i)
{
    const int c  = blockIdx.y;
    const int d0 = blockIdx.x * 256;
    __shared__ __align__(16) float pes[NPRO * OCH];

    const int tid = threadIdx.x;
    {
        const float4* src = (const float4*)(g_pe + (size_t)c * NPRO * OCH);
        float4* dst = (float4*)pes;
        for (int i = tid; i < NPRO * OCH / 4; i += 256) dst[i] = src[i];
    }
    __syncthreads();

    const int d = d0 + tid;
    float acc[NPRO] = {0.f, 0.f, 0.f, 0.f, 0.f};
#pragma unroll 8
    for (int o = 0; o < OCH; ++o) {
        float wv = w1i[(size_t)o * DIM + d];
#pragma unroll
        for (int p = 0; p < NPRO; ++p) acc[p] += pes[p * OCH + o] * wv;
    }
#pragma unroll
    for (int p = 0; p < NPRO; ++p)
        g_q[((size_t)c * NPRO + p) * DIM + d] = acc[p];
}

__global__ __launch_bounds__(256) void kC3()
{
    const int c  = blockIdx.y;
    const int n0 = blockIdx.x * 32;
    __shared__ __align__(16) float qsm[NPRO * DIM];

    const int tid = threadIdx.x;
    const int lane = tid & 31;
    const int w = tid >> 5;
    const float* F = g_feats + (size_t)c * (NGRP * NSEQ) * DIM;

    {
        const float4* src = (const float4*)(g_q + (size_t)c * NPRO * DIM);
        float4* dst = (float4*)qsm;
        for (int i = tid; i < NPRO * DIM / 4; i += 256) dst[i] = src[i];
    }
    __syncthreads();

#pragma unroll
    for (int ni = 0; ni < 4; ++ni) {
        int n = n0 + w * 4 + ni;
        const float* fr = F + (size_t)n * DIM;
        float acc[NPRO] = {0.f, 0.f, 0.f, 0.f, 0.f};
        for (int d = lane; d < DIM; d += 32) {
            float fv = fr[d];
#pragma unroll
            for (int p = 0; p < NPRO; ++p) acc[p] += fv * qsm[p * DIM + d];
        }
#pragma unroll
        for (int p = 0; p < NPRO; ++p) {
#pragma unroll
            for (int off = 16; off > 0; off >>= 1)
                acc[p] += __shfl_xor_sync(0xffffffffu, acc[p], off);
        }
        if (lane == 0) {
#pragma unroll
            for (int p = 0; p < NPRO; ++p)
                g_s[((size_t)c * NPRO + p) * OCH + n] = acc[p] * 0.0625f;
        }
    }
}

__global__ __launch_bounds__(256) void kC4(float* __restrict__ outp)
{
    const int c  = blockIdx.y;
    const int d0 = blockIdx.x * 256;
    __shared__ __align__(16) float att[NPRO * OCH];

    const int tid = threadIdx.x;
    const int lane = tid & 31;
    const int w = tid >> 5;
    const float* F = g_feats + (size_t)c * (NGRP * NSEQ) * DIM;

    {
        const float4* src = (const float4*)(g_s + (size_t)c * NPRO * OCH);
        float4* dst = (float4*)att;
        for (int i = tid; i < NPRO * OCH / 4; i += 256) dst[i] = src[i];
    }
    __syncthreads();

    if (w < NPRO) {
        const int p = w;
        float mx = -1e30f;
        for (int n = lane; n < OCH; n += 32) mx = fmaxf(mx, att[p * OCH + n]);
#pragma unroll
        for (int off = 16; off > 0; off >>= 1)
            mx = fmaxf(mx, __shfl_xor_sync(0xffffffffu, mx, off));
        float sm = 0.f;
        for (int n = lane; n < OCH; n += 32) {
            float e = expf(att[p * OCH + n] - mx);
            att[p * OCH + n] = e;
            sm += e;
        }
#pragma unroll
        for (int off = 16; off > 0; off >>= 1)
            sm += __shfl_xor_sync(0xffffffffu, sm, off);
        float inv = 1.f / sm;
        for (int n = lane; n < OCH; n += 32) att[p * OCH + n] *= inv;
    }
    __syncthreads();

    const int d = d0 + tid;
    float acc[NPRO] = {0.f, 0.f, 0.f, 0.f, 0.f};
#pragma unroll 8
    for (int n = 0; n < OCH; ++n) {
        float fv = F[(size_t)n * DIM + d];
#pragma unroll
        for (int p = 0; p < NPRO; ++p) acc[p] += att[p * OCH + n] * fv;
    }
    float* ob = outp + (size_t)c * NPRO * DIM;
#pragma unroll
    for (int p = 0; p < NPRO; ++p) ob[(size_t)p * DIM + d] = acc[p];
}

// ---------------------------------------------------------------------------
extern "C" void kernel_launch(void* const* d_in, const int* in_sizes, int n_in,
                              void* d_out, int out_size)
{
    const float* topk   = (const float*)d_in[0];  // [64,8,32,2048]
    const float* protos = (const float*)d_in[1];  // [64,5,2048]
    const float* w1     = (const float*)d_in[2];  // [256,2048]
    const float* trans  = (const float*)d_in[3];  // [2048,2048]
    const float* w1i    = (const float*)d_in[4];  // [256,2048]
    const float* w2i    = (const float*)d_in[5];  // [256,2048]
    float* out = (float*)d_out;

    // pre-convert weights: trans -> bf16, w1 -> tf32
    __nv_bfloat16* trh = nullptr; cudaGetSymbolAddress((void**)&trh, g_trh);
    float* w1r = nullptr; cudaGetSymbolAddress((void**)&w1r, g_w1r);
    kTh<<<1024, 256>>>(trans, trh, DIM * DIM / 4);
    kT<<<64, 256>>>(w1, w1r, OCH * DIM / 4);

    dim3 gA1(OCH / 128, MTOT / 128);  // (2, 128)
    kA1<<<gA1, 256>>>(topk);
    kA2<<<NCLS * NGRP, 256>>>(topk);

    dim3 gB(DIM / 128, MTOT / 128);   // (16, 128)
    kB<<<gB, 256>>>(topk);

    dim3 gC(8, NCLS);                 // (8, 64)
    kC1<<<gC, 256>>>(protos, w2i);
    kC2<<<gC, 256>>>(w1i);
    kC3<<<gC, 256>>>();
    kC4<<<gC, 256>>>(out);
}